// round 9
// baseline (speedup 1.0000x reference)
#include <cuda_runtime.h>
#include <cuda_bf16.h>
#include <math.h>
#include <stdint.h>

#define BATCH 8
#define CCH 192
#define HEADS 16
#define HD 12
#define HW 16384
#define SSPLIT 16
#define SKCH 1024   // HW / SSPLIT

// ---------------- scratch (device globals; no allocation) ----------------
__device__ float g_Spart[BATCH * SSPLIT * CCH * CCH];
__device__ float g_S[BATCH * CCH * CCH];
__device__ float g_Y[(size_t)BATCH * CCH * HW];                 // attention output fp32
__device__ unsigned short g_MHi[BATCH * CCH * CCH];             // Meff bf16 hi
__device__ unsigned short g_MLo[BATCH * CCH * CCH];             // Meff bf16 lo
__device__ unsigned short g_WHi[CCH * CCH];                     // Wproj bf16 hi
__device__ unsigned short g_WLo[CCH * CCH];
__device__ unsigned short g_Xhi[(size_t)BATCH * CCH * HW];      // X bf16 hi [b][c][p]
__device__ unsigned short g_Xlo[(size_t)BATCH * CCH * HW];
__device__ unsigned short g_XThi[(size_t)BATCH * HW * CCH];     // X^T bf16 hi [b][p][k]
__device__ unsigned short g_XTlo[(size_t)BATCH * HW * CCH];
__device__ unsigned short g_ZThi[(size_t)BATCH * HW * CCH];     // dw(Y)^T bf16 hi [b][p][c]
__device__ unsigned short g_ZTlo[(size_t)BATCH * HW * CCH];

__constant__ int c_tm[6] = {0, 0, 0, 1, 1, 2};
__constant__ int c_tn[6] = {0, 1, 2, 1, 2, 2};

__device__ __forceinline__ void split_bf16(float v, unsigned short& h, unsigned short& l) {
    __nv_bfloat16 bh = __float2bfloat16(v);
    float hf = __bfloat162float(bh);
    __nv_bfloat16 bl = __float2bfloat16(v - hf);
    h = __bfloat16_as_ushort(bh);
    l = __bfloat16_as_ushort(bl);
}

__device__ __forceinline__ uint32_t smem_to_u32(const void* smem_ptr) {
    uint32_t addr;
    asm("{ .reg .u64 tmp; cvta.to.shared.u64 tmp, %1; cvt.u32.u64 %0, tmp; }"
        : "=r"(addr) : "l"(smem_ptr));
    return addr;
}
__device__ __forceinline__ void cp_async16(uint32_t dst, const void* src) {
    asm volatile("cp.async.cg.shared.global [%0], [%1], 16;" :: "r"(dst), "l"(src) : "memory");
}
#define CP_COMMIT() asm volatile("cp.async.commit_group;" ::: "memory")
#define CP_WAIT(n)  asm volatile("cp.async.wait_group %0;" :: "n"(n) : "memory")

__device__ __forceinline__ void mma_bf16(float* c, const uint32_t* a, const uint32_t* b) {
    asm volatile(
        "mma.sync.aligned.m16n8k16.row.col.f32.bf16.bf16.f32 "
        "{%0,%1,%2,%3}, {%4,%5,%6,%7}, {%8,%9}, {%0,%1,%2,%3};"
        : "+f"(c[0]), "+f"(c[1]), "+f"(c[2]), "+f"(c[3])
        : "r"(a[0]), "r"(a[1]), "r"(a[2]), "r"(a[3]), "r"(b[0]), "r"(b[1]));
}

// ---------------- kernel 1: S partials = X X^T via mma (split-bf16) ----------
// grid (6 upper tile-pairs, SSPLIT, BATCH), 128 threads.
// 64x64 tile, warp grid 2x2 (warp tile 32x32), K-chunk 1024, cp.async x2 buf.
#define S_SA 20      // smem row stride in u32 (32 k = 16 u32 + 4 pad)
#define S_AHI 0
#define S_ALO 1280
#define S_BHI 2560
#define S_BLO 3840
#define S_BUF 5120

__global__ void __launch_bounds__(128, 2) s_mma_kernel() {
    __shared__ uint32_t sm32[2 * S_BUF];

    const int tm = c_tm[blockIdx.x], tn = c_tn[blockIdx.x];
    const int ks = blockIdx.y, b = blockIdx.z;
    const int t = threadIdx.x;
    const int warp = t >> 5, lane = t & 31;
    const int wm = warp & 1, wn = warp >> 1;
    const int warpM = wm * 32, warpN = wn * 32;
    const int gr = lane >> 2, qp = lane & 3;

    const size_t k0 = (size_t)ks * SKCH;
    const unsigned short* Ah = g_Xhi + ((size_t)b * CCH + tm * 64) * HW + k0;
    const unsigned short* Al = g_Xlo + ((size_t)b * CCH + tm * 64) * HW + k0;
    const unsigned short* Bh = g_Xhi + ((size_t)b * CCH + tn * 64) * HW + k0;
    const unsigned short* Bl = g_Xlo + ((size_t)b * CCH + tn * 64) * HW + k0;

    const uint32_t smbase = smem_to_u32(sm32);

    float acc[2][4][4] = {};

    auto issue_chunk = [&](int buf, int kc) {
        const uint32_t sb = smbase + buf * (S_BUF * 4);
        const int kb = kc * 32;
        // 64 rows x 4 quads per stream; 256 items, 2 per thread, 4 streams
#pragma unroll
        for (int i = t; i < 256; i += 128) {
            int row = i >> 2, q = i & 3;
            uint32_t dst = sb + (row * S_SA + q * 4) * 4;
            const size_t off = (size_t)row * HW + kb + q * 8;
            cp_async16(dst + S_AHI * 4, Ah + off);
            cp_async16(dst + S_ALO * 4, Al + off);
            cp_async16(dst + S_BHI * 4, Bh + off);
            cp_async16(dst + S_BLO * 4, Bl + off);
        }
        CP_COMMIT();
    };

    issue_chunk(0, 0);

    int buf = 0;
    const int NIT = SKCH / 32;   // 32
    for (int kc = 0; kc < NIT; kc++) {
        if (kc < NIT - 1) {
            issue_chunk(buf ^ 1, kc + 1);
            CP_WAIT(1);
        } else {
            CP_WAIT(0);
        }
        __syncthreads();

        const uint32_t* S = sm32 + buf * S_BUF;
#pragma unroll
        for (int kk = 0; kk < 2; kk++) {
            const int k8 = kk * 8;
            uint32_t ah[2][4], al[2][4], bh[4][2], bl[4][2];
#pragma unroll
            for (int mt = 0; mt < 2; mt++) {
                int base = (warpM + mt * 16 + gr) * S_SA + k8 + qp;
                ah[mt][0] = S[S_AHI + base];     ah[mt][1] = S[S_AHI + base + 8 * S_SA];
                ah[mt][2] = S[S_AHI + base + 4]; ah[mt][3] = S[S_AHI + base + 8 * S_SA + 4];
                al[mt][0] = S[S_ALO + base];     al[mt][1] = S[S_ALO + base + 8 * S_SA];
                al[mt][2] = S[S_ALO + base + 4]; al[mt][3] = S[S_ALO + base + 8 * S_SA + 4];
            }
#pragma unroll
            for (int nt = 0; nt < 4; nt++) {
                int base = (warpN + nt * 8 + gr) * S_SA + k8 + qp;
                bh[nt][0] = S[S_BHI + base]; bh[nt][1] = S[S_BHI + base + 4];
                bl[nt][0] = S[S_BLO + base]; bl[nt][1] = S[S_BLO + base + 4];
            }
#pragma unroll
            for (int mt = 0; mt < 2; mt++)
#pragma unroll
                for (int nt = 0; nt < 4; nt++) {
                    mma_bf16(acc[mt][nt], ah[mt], bh[nt]);
                    mma_bf16(acc[mt][nt], ah[mt], bl[nt]);
                    mma_bf16(acc[mt][nt], al[mt], bh[nt]);
                }
        }
        __syncthreads();
        buf ^= 1;
    }

    float* sp = g_Spart + (size_t)(b * SSPLIT + ks) * CCH * CCH;
#pragma unroll
    for (int mt = 0; mt < 2; mt++) {
        int m = tm * 64 + warpM + mt * 16 + gr;
        float* r0 = sp + (size_t)m * CCH + tn * 64 + warpN + qp * 2;
        float* r1 = sp + (size_t)(m + 8) * CCH + tn * 64 + warpN + qp * 2;
#pragma unroll
        for (int nt = 0; nt < 4; nt++) {
            *(float2*)(r0 + nt * 8) = make_float2(acc[mt][nt][0], acc[mt][nt][1]);
            *(float2*)(r1 + nt * 8) = make_float2(acc[mt][nt][2], acc[mt][nt][3]);
        }
    }
}

// ---------------- kernel 2: reduce split-K partials (mirror lower) ----------
__global__ void s_reduce_kernel() {
    int gid = blockIdx.x * blockDim.x + threadIdx.x;
    if (gid >= BATCH * CCH * CCH) return;
    int b = gid / (CCH * CCH), mn = gid % (CCH * CCH);
    int m = mn / CCH, n = mn % CCH;
    int off = ((m >> 6) <= (n >> 6)) ? (m * CCH + n) : (n * CCH + m);
    const float* base = g_Spart + (size_t)b * SSPLIT * CCH * CCH;
    float s = 0.f;
#pragma unroll
    for (int ks = 0; ks < SSPLIT; ks++)
        s += base[(size_t)ks * CCH * CCH + off];
    g_S[gid] = s;
}

// ---------------- kernel 3: per-(b,h) attention -> Meff (bf16 hi/lo) --------
__global__ void attn_build_kernel(const float* __restrict__ w_qkv,
                                  const float* __restrict__ temperature) {
    const int h = blockIdx.x, b = blockIdx.y, t = threadIdx.x;

    __shared__ float sWq[HD][196];
    __shared__ float sWk[HD][196];
    __shared__ float sT[2 * HD][196];
    __shared__ float sG[HD][HD];
    __shared__ float sAttn[HD][HD];
    __shared__ float sQn[HD], sKn[HD];

    for (int i = t; i < HD * CCH; i += 192) {
        int c = i / CCH, j = i % CCH;
        sWq[c][j] = w_qkv[(h * HD + c) * CCH + j];
        sWk[c][j] = w_qkv[(CCH + h * HD + c) * CCH + j];
    }
    __syncthreads();

    {
        float tq[HD] = {}, tk[HD] = {};
        const float* Sb = g_S + b * CCH * CCH;
        for (int m = 0; m < CCH; m++) {
            float s = Sb[m * CCH + t];
#pragma unroll
            for (int c = 0; c < HD; c++) { tq[c] += sWq[c][m] * s; tk[c] += sWk[c][m] * s; }
        }
#pragma unroll
        for (int c = 0; c < HD; c++) { sT[c][t] = tq[c]; sT[HD + c][t] = tk[c]; }
    }
    __syncthreads();

    if (t < 144) {
        int c = t / HD, d = t % HD;
        float s = 0.f;
        for (int j = 0; j < CCH; j++) s += sT[c][j] * sWk[d][j];
        sG[c][d] = s;
    } else if (t < 156) {
        int c = t - 144; float s = 0.f;
        for (int j = 0; j < CCH; j++) s += sT[c][j] * sWq[c][j];
        sQn[c] = s;
    } else if (t < 168) {
        int c = t - 156; float s = 0.f;
        for (int j = 0; j < CCH; j++) s += sT[HD + c][j] * sWk[c][j];
        sKn[c] = s;
    }
    __syncthreads();

    if (t < HD) {
        float temp = temperature[h];
        float qn = fmaxf(sqrtf(fmaxf(sQn[t], 0.f)), 1e-12f);
        float lg[HD];
        float mx = -1e30f;
#pragma unroll
        for (int d = 0; d < HD; d++) {
            float kn = fmaxf(sqrtf(fmaxf(sKn[d], 0.f)), 1e-12f);
            lg[d] = sG[t][d] * temp / (qn * kn);
            mx = fmaxf(mx, lg[d]);
        }
        float sum = 0.f;
#pragma unroll
        for (int d = 0; d < HD; d++) { lg[d] = expf(lg[d] - mx); sum += lg[d]; }
        float inv = 1.f / sum;
#pragma unroll
        for (int d = 0; d < HD; d++) sAttn[t][d] = lg[d] * inv;
    }
    float (*sWv)[196] = sT;
    for (int i = t; i < HD * CCH; i += 192) {
        int c = i / CCH, j = i % CCH;
        sWv[c][j] = w_qkv[(2 * CCH + h * HD + c) * CCH + j];
    }
    __syncthreads();

#pragma unroll
    for (int c = 0; c < HD; c++) {
        float s = 0.f;
#pragma unroll
        for (int d = 0; d < HD; d++) s += sAttn[c][d] * sWv[d][t];
        size_t idx = (size_t)(b * CCH + h * HD + c) * CCH + t;
        unsigned short hh, ll;
        split_bf16(s, hh, ll);
        g_MHi[idx] = hh; g_MLo[idx] = ll;
    }
}

// ---------------- kernel 3b: Wproj -> bf16 hi/lo ----------------------------
__global__ void wconv_kernel(const float* __restrict__ w_proj) {
    int gid = blockIdx.x * blockDim.x + threadIdx.x;
    if (gid >= CCH * CCH) return;
    unsigned short hh, ll;
    split_bf16(w_proj[gid], hh, ll);
    g_WHi[gid] = hh; g_WLo[gid] = ll;
}

// ---------------- kernel 3c: X -> XT hi/lo [b][p][k]  AND X hi/lo [b][k][p] --
__global__ void xt_kernel(const float* __restrict__ x) {
    const int b = blockIdx.z;
    const int k0 = blockIdx.y * 32, p0 = blockIdx.x * 32;
    __shared__ float sm[32][33];
    const int tx = threadIdx.x & 31, ty = threadIdx.x >> 5;

#pragma unroll
    for (int i = 0; i < 4; i++) {
        int k = k0 + ty + i * 8;
        float v = x[((size_t)b * CCH + k) * HW + p0 + tx];
        sm[ty + i * 8][tx] = v;
        unsigned short hh, ll;
        split_bf16(v, hh, ll);
        size_t o = ((size_t)b * CCH + k) * HW + p0 + tx;
        g_Xhi[o] = hh;
        g_Xlo[o] = ll;
    }
    __syncthreads();
#pragma unroll
    for (int i = 0; i < 4; i++) {
        int p = p0 + ty + i * 8;
        int k = k0 + tx;
        float v = sm[tx][ty + i * 8];
        unsigned short hh, ll;
        split_bf16(v, hh, ll);
        size_t o = ((size_t)b * HW + p) * CCH + k;
        g_XThi[o] = hh;
        g_XTlo[o] = ll;
    }
}

// ---------------- kernel 4: mma.sync GEMM  C[b] = A[b] @ B[b]^T ---------------
#define SA32 20                 // smem row stride in u32 (40 bf16)
#define BUF_U32 12800           // per-buffer u32 size
#define OFF_ALO 3840
#define OFF_BHI 7680
#define OFF_BLO 10240
#define GEMM_SMEM (2 * BUF_U32 * 4)   // 102400 bytes

__global__ void __launch_bounds__(256, 1)
gemm_mma_kernel(const unsigned short* __restrict__ Ahi,
                const unsigned short* __restrict__ Alo,
                size_t aStride,
                const unsigned short* __restrict__ BThi,
                const unsigned short* __restrict__ BTlo,
                float* __restrict__ C) {
    extern __shared__ uint32_t sm32[];
    const int t = threadIdx.x;
    const int b = blockIdx.z;
    const int n0 = blockIdx.x * 128;
    const int warp = t >> 5, lane = t & 31;
    const int wm = warp & 3, wn = warp >> 2;
    const int warpM = wm * 48, warpN = wn * 64;
    const int gr = lane >> 2, qp = lane & 3;

    const unsigned short* Ah = Ahi + (size_t)b * aStride;
    const unsigned short* Al = Alo + (size_t)b * aStride;
    const unsigned short* Bh = BThi + ((size_t)b * HW + n0) * CCH;
    const unsigned short* Bl = BTlo + ((size_t)b * HW + n0) * CCH;

    const uint32_t smbase = smem_to_u32(sm32);

    float acc[3][8][4] = {};

    auto issue_chunk = [&](int buf, int kc) {
        const uint32_t sb = smbase + buf * (BUF_U32 * 4);
        const int kb = kc * 32;
#pragma unroll
        for (int i = t; i < 768; i += 256) {
            int row = i >> 2, q = i & 3;
            uint32_t dst = sb + (row * SA32 + q * 4) * 4;
            cp_async16(dst,                Ah + (size_t)row * CCH + kb + q * 8);
            cp_async16(dst + OFF_ALO * 4,  Al + (size_t)row * CCH + kb + q * 8);
        }
#pragma unroll
        for (int i = t; i < 512; i += 256) {
            int row = i >> 2, q = i & 3;
            uint32_t dst = sb + (OFF_BHI + row * SA32 + q * 4) * 4;
            cp_async16(dst,                       Bh + (size_t)row * CCH + kb + q * 8);
            cp_async16(dst + (OFF_BLO - OFF_BHI) * 4, Bl + (size_t)row * CCH + kb + q * 8);
        }
        CP_COMMIT();
    };

    issue_chunk(0, 0);

    int buf = 0;
    for (int kc = 0; kc < 6; kc++) {
        if (kc < 5) {
            issue_chunk(buf ^ 1, kc + 1);
            CP_WAIT(1);
        } else {
            CP_WAIT(0);
        }
        __syncthreads();

        const uint32_t* S = sm32 + buf * BUF_U32;
#pragma unroll
        for (int ks = 0; ks < 2; ks++) {
            const int k8 = ks * 8;
            uint32_t ah[3][4], al[3][4], bh[8][2], bl[8][2];
#pragma unroll
            for (int mt = 0; mt < 3; mt++) {
                int base = (warpM + mt * 16 + gr) * SA32 + k8 + qp;
                ah[mt][0] = S[base];           ah[mt][1] = S[base + 8 * SA32];
                ah[mt][2] = S[base + 4];       ah[mt][3] = S[base + 8 * SA32 + 4];
                al[mt][0] = S[OFF_ALO + base];           al[mt][1] = S[OFF_ALO + base + 8 * SA32];
                al[mt][2] = S[OFF_ALO + base + 4];       al[mt][3] = S[OFF_ALO + base + 8 * SA32 + 4];
            }
#pragma unroll
            for (int nt = 0; nt < 8; nt++) {
                int base = (warpN + nt * 8 + gr) * SA32 + k8 + qp;
                bh[nt][0] = S[OFF_BHI + base]; bh[nt][1] = S[OFF_BHI + base + 4];
                bl[nt][0] = S[OFF_BLO + base]; bl[nt][1] = S[OFF_BLO + base + 4];
            }
#pragma unroll
            for (int mt = 0; mt < 3; mt++)
#pragma unroll
                for (int nt = 0; nt < 8; nt++) {
                    mma_bf16(acc[mt][nt], ah[mt], bh[nt]);
                    mma_bf16(acc[mt][nt], ah[mt], bl[nt]);
                    mma_bf16(acc[mt][nt], al[mt], bh[nt]);
                }
        }
        __syncthreads();
        buf ^= 1;
    }

#pragma unroll
    for (int mt = 0; mt < 3; mt++) {
        int m = warpM + mt * 16 + gr;
        float* c0 = C + ((size_t)b * CCH + m) * HW + n0 + warpN + qp * 2;
        float* c1 = C + ((size_t)b * CCH + m + 8) * HW + n0 + warpN + qp * 2;
#pragma unroll
        for (int nt = 0; nt < 8; nt++) {
            *(float2*)(c0 + nt * 8) = make_float2(acc[mt][nt][0], acc[mt][nt][1]);
            *(float2*)(c1 + nt * 8) = make_float2(acc[mt][nt][2], acc[mt][nt][3]);
        }
    }
}

// ---------------- kernel 6: depthwise 3x3 -> Z^T bf16 hi/lo [b][p][c] --------
__global__ void dwconv_t_kernel(const float* __restrict__ wdw) {
    const int b = blockIdx.z;
    const int c0 = blockIdx.y * 32;
    const int p0 = blockIdx.x * 32;
    const int y  = p0 >> 7;
    const int x0 = p0 & 127;

    __shared__ float sw[32][9];
    __shared__ float st[32][33];   // [px][chLocal]

    const int t = threadIdx.x;
    for (int idx = t; idx < 288; idx += 256)
        sw[idx / 9][idx % 9] = wdw[(c0 + idx / 9) * 9 + idx % 9];
    __syncthreads();

    const int tx = t & 31;      // px
    const int tg = t >> 5;      // 0..7
    const int xx = x0 + tx;

#pragma unroll
    for (int i = 0; i < 4; i++) {
        int chL = tg + i * 8;
        const float* Yc = g_Y + ((size_t)b * CCH + c0 + chL) * HW;
        float acc = 0.f;
#pragma unroll
        for (int ky = 0; ky < 3; ky++) {
            int sy = y + ky - 1;
            if (sy < 0 || sy >= 128) continue;
#pragma unroll
            for (int kx = 0; kx < 3; kx++) {
                int sx = xx + kx - 1;
                if (sx < 0 || sx >= 128) continue;
                acc += sw[chL][ky * 3 + kx] * __ldg(Yc + sy * 128 + sx);
            }
        }
        st[tx][chL] = acc;
    }
    __syncthreads();

    const int row = t >> 3;
    const int ch4 = (t & 7) * 4;
    float v0 = st[row][ch4 + 0], v1 = st[row][ch4 + 1];
    float v2 = st[row][ch4 + 2], v3 = st[row][ch4 + 3];
    unsigned short h0, l0, h1, l1, h2, l2, h3, l3;
    split_bf16(v0, h0, l0); split_bf16(v1, h1, l1);
    split_bf16(v2, h2, l2); split_bf16(v3, h3, l3);
    size_t o = ((size_t)b * HW + p0 + row) * CCH + c0 + ch4;
    *(uint32_t*)(g_ZThi + o)     = (uint32_t)h0 | ((uint32_t)h1 << 16);
    *(uint32_t*)(g_ZThi + o + 2) = (uint32_t)h2 | ((uint32_t)h3 << 16);
    *(uint32_t*)(g_ZTlo + o)     = (uint32_t)l0 | ((uint32_t)l1 << 16);
    *(uint32_t*)(g_ZTlo + o + 2) = (uint32_t)l2 | ((uint32_t)l3 << 16);
}

// ---------------- launch ----------------
extern "C" void kernel_launch(void* const* d_in, const int* in_sizes, int n_in,
                              void* d_out, int out_size) {
    const float* x           = (const float*)d_in[0];
    const float* w_qkv       = (const float*)d_in[1];
    const float* w_dw        = (const float*)d_in[2];
    const float* w_proj      = (const float*)d_in[3];
    const float* temperature = (const float*)d_in[4];
    float* out = (float*)d_out;

    cudaFuncSetAttribute(gemm_mma_kernel,
                         cudaFuncAttributeMaxDynamicSharedMemorySize, GEMM_SMEM);

    float* pY;
    unsigned short *pMHi, *pMLo, *pWHi, *pWLo, *pXThi, *pXTlo, *pZThi, *pZTlo;
    cudaGetSymbolAddress((void**)&pY, g_Y);
    cudaGetSymbolAddress((void**)&pMHi, g_MHi);
    cudaGetSymbolAddress((void**)&pMLo, g_MLo);
    cudaGetSymbolAddress((void**)&pWHi, g_WHi);
    cudaGetSymbolAddress((void**)&pWLo, g_WLo);
    cudaGetSymbolAddress((void**)&pXThi, g_XThi);
    cudaGetSymbolAddress((void**)&pXTlo, g_XTlo);
    cudaGetSymbolAddress((void**)&pZThi, g_ZThi);
    cudaGetSymbolAddress((void**)&pZTlo, g_ZTlo);

    // 0) X -> bf16 hi/lo in both layouts
    xt_kernel<<<dim3(HW / 32, CCH / 32, BATCH), 256>>>(x);
    wconv_kernel<<<(CCH * CCH + 255) / 256, 256>>>(w_proj);

    // 1) S = X X^T (tensor-core split-K partials + deterministic mirror-reduce)
    s_mma_kernel<<<dim3(6, SSPLIT, BATCH), 128>>>();
    s_reduce_kernel<<<(BATCH * CCH * CCH + 255) / 256, 256>>>();

    // 2) attention -> Meff (bf16 hi/lo)
    attn_build_kernel<<<dim3(HEADS, BATCH), 192>>>(w_qkv, temperature);

    // 3) Y = Meff @ X   (mma.sync split-bf16)
    gemm_mma_kernel<<<dim3(HW / 128, 1, BATCH), 256, GEMM_SMEM>>>(
        pMHi, pMLo, (size_t)CCH * CCH, pXThi, pXTlo, pY);

    // 4) depthwise 3x3 -> Z^T bf16 hi/lo
    dwconv_t_kernel<<<dim3(HW / 32, CCH / 32, BATCH), 256>>>(w_dw);

    // 5) out = Wproj @ Z   (mma.sync split-bf16)
    gemm_mma_kernel<<<dim3(HW / 128, 1, BATCH), 256, GEMM_SMEM>>>(
        pWHi, pWLo, (size_t)0, pZThi, pZTlo, out);
}

// round 10
// speedup vs baseline: 1.0002x; 1.0002x over previous
#include <cuda_runtime.h>
#include <cuda_bf16.h>
#include <math.h>
#include <stdint.h>

#define BATCH 8
#define CCH 192
#define HEADS 16
#define HD 12
#define HW 16384
#define SSPLIT 16
#define SKCH 1024   // HW / SSPLIT

// ---------------- scratch (device globals; no allocation) ----------------
__device__ float g_Spart[BATCH * SSPLIT * CCH * CCH];
__device__ float g_S[BATCH * CCH * CCH];
__device__ float g_Y[(size_t)BATCH * CCH * HW];                 // attention output fp32
__device__ unsigned short g_MHi[BATCH * CCH * CCH];             // Meff bf16 hi
__device__ unsigned short g_MLo[BATCH * CCH * CCH];             // Meff bf16 lo
__device__ unsigned short g_WHi[CCH * CCH];                     // Wproj bf16 hi
__device__ unsigned short g_WLo[CCH * CCH];
__device__ unsigned short g_Xhi[(size_t)BATCH * CCH * HW];      // X bf16 hi [b][c][p]
__device__ unsigned short g_Xlo[(size_t)BATCH * CCH * HW];
__device__ unsigned short g_XThi[(size_t)BATCH * HW * CCH];     // X^T bf16 hi [b][p][k]
__device__ unsigned short g_XTlo[(size_t)BATCH * HW * CCH];
__device__ unsigned short g_ZThi[(size_t)BATCH * HW * CCH];     // dw(Y)^T bf16 hi [b][p][c]
__device__ unsigned short g_ZTlo[(size_t)BATCH * HW * CCH];

__constant__ int c_tm[6] = {0, 0, 0, 1, 1, 2};
__constant__ int c_tn[6] = {0, 1, 2, 1, 2, 2};

__device__ __forceinline__ void split_bf16(float v, unsigned short& h, unsigned short& l) {
    __nv_bfloat16 bh = __float2bfloat16(v);
    float hf = __bfloat162float(bh);
    __nv_bfloat16 bl = __float2bfloat16(v - hf);
    h = __bfloat16_as_ushort(bh);
    l = __bfloat16_as_ushort(bl);
}

__device__ __forceinline__ uint32_t smem_to_u32(const void* smem_ptr) {
    uint32_t addr;
    asm("{ .reg .u64 tmp; cvta.to.shared.u64 tmp, %1; cvt.u32.u64 %0, tmp; }"
        : "=r"(addr) : "l"(smem_ptr));
    return addr;
}
__device__ __forceinline__ void cp_async16(uint32_t dst, const void* src) {
    asm volatile("cp.async.cg.shared.global [%0], [%1], 16;" :: "r"(dst), "l"(src) : "memory");
}
#define CP_COMMIT() asm volatile("cp.async.commit_group;" ::: "memory")
#define CP_WAIT(n)  asm volatile("cp.async.wait_group %0;" :: "n"(n) : "memory")

__device__ __forceinline__ void mma_bf16(float* c, const uint32_t* a, const uint32_t* b) {
    asm volatile(
        "mma.sync.aligned.m16n8k16.row.col.f32.bf16.bf16.f32 "
        "{%0,%1,%2,%3}, {%4,%5,%6,%7}, {%8,%9}, {%0,%1,%2,%3};"
        : "+f"(c[0]), "+f"(c[1]), "+f"(c[2]), "+f"(c[3])
        : "r"(a[0]), "r"(a[1]), "r"(a[2]), "r"(a[3]), "r"(b[0]), "r"(b[1]));
}

// ---------------- kernel 1: S partials = X X^T via mma (split-bf16) ----------
// grid (6 upper tile-pairs, SSPLIT, BATCH), 128 threads.
// 64x64 tile, warp grid 2x2 (warp tile 32x32), K-chunk 1024, cp.async x2 buf.
#define S_SA 20      // smem row stride in u32 (32 k = 16 u32 + 4 pad)
#define S_AHI 0
#define S_ALO 1280
#define S_BHI 2560
#define S_BLO 3840
#define S_BUF 5120

__global__ void __launch_bounds__(128, 2) s_mma_kernel() {
    __shared__ uint32_t sm32[2 * S_BUF];

    const int tm = c_tm[blockIdx.x], tn = c_tn[blockIdx.x];
    const int ks = blockIdx.y, b = blockIdx.z;
    const int t = threadIdx.x;
    const int warp = t >> 5, lane = t & 31;
    const int wm = warp & 1, wn = warp >> 1;
    const int warpM = wm * 32, warpN = wn * 32;
    const int gr = lane >> 2, qp = lane & 3;

    const size_t k0 = (size_t)ks * SKCH;
    const unsigned short* Ah = g_Xhi + ((size_t)b * CCH + tm * 64) * HW + k0;
    const unsigned short* Al = g_Xlo + ((size_t)b * CCH + tm * 64) * HW + k0;
    const unsigned short* Bh = g_Xhi + ((size_t)b * CCH + tn * 64) * HW + k0;
    const unsigned short* Bl = g_Xlo + ((size_t)b * CCH + tn * 64) * HW + k0;

    const uint32_t smbase = smem_to_u32(sm32);

    float acc[2][4][4] = {};

    auto issue_chunk = [&](int buf, int kc) {
        const uint32_t sb = smbase + buf * (S_BUF * 4);
        const int kb = kc * 32;
        // 64 rows x 4 quads per stream; 256 items, 2 per thread, 4 streams
#pragma unroll
        for (int i = t; i < 256; i += 128) {
            int row = i >> 2, q = i & 3;
            uint32_t dst = sb + (row * S_SA + q * 4) * 4;
            const size_t off = (size_t)row * HW + kb + q * 8;
            cp_async16(dst + S_AHI * 4, Ah + off);
            cp_async16(dst + S_ALO * 4, Al + off);
            cp_async16(dst + S_BHI * 4, Bh + off);
            cp_async16(dst + S_BLO * 4, Bl + off);
        }
        CP_COMMIT();
    };

    issue_chunk(0, 0);

    int buf = 0;
    const int NIT = SKCH / 32;   // 32
    for (int kc = 0; kc < NIT; kc++) {
        if (kc < NIT - 1) {
            issue_chunk(buf ^ 1, kc + 1);
            CP_WAIT(1);
        } else {
            CP_WAIT(0);
        }
        __syncthreads();

        const uint32_t* S = sm32 + buf * S_BUF;
#pragma unroll
        for (int kk = 0; kk < 2; kk++) {
            const int k8 = kk * 8;
            uint32_t ah[2][4], al[2][4], bh[4][2], bl[4][2];
#pragma unroll
            for (int mt = 0; mt < 2; mt++) {
                int base = (warpM + mt * 16 + gr) * S_SA + k8 + qp;
                ah[mt][0] = S[S_AHI + base];     ah[mt][1] = S[S_AHI + base + 8 * S_SA];
                ah[mt][2] = S[S_AHI + base + 4]; ah[mt][3] = S[S_AHI + base + 8 * S_SA + 4];
                al[mt][0] = S[S_ALO + base];     al[mt][1] = S[S_ALO + base + 8 * S_SA];
                al[mt][2] = S[S_ALO + base + 4]; al[mt][3] = S[S_ALO + base + 8 * S_SA + 4];
            }
#pragma unroll
            for (int nt = 0; nt < 4; nt++) {
                int base = (warpN + nt * 8 + gr) * S_SA + k8 + qp;
                bh[nt][0] = S[S_BHI + base]; bh[nt][1] = S[S_BHI + base + 4];
                bl[nt][0] = S[S_BLO + base]; bl[nt][1] = S[S_BLO + base + 4];
            }
#pragma unroll
            for (int mt = 0; mt < 2; mt++)
#pragma unroll
                for (int nt = 0; nt < 4; nt++) {
                    mma_bf16(acc[mt][nt], ah[mt], bh[nt]);
                    mma_bf16(acc[mt][nt], ah[mt], bl[nt]);
                    mma_bf16(acc[mt][nt], al[mt], bh[nt]);
                }
        }
        __syncthreads();
        buf ^= 1;
    }

    float* sp = g_Spart + (size_t)(b * SSPLIT + ks) * CCH * CCH;
#pragma unroll
    for (int mt = 0; mt < 2; mt++) {
        int m = tm * 64 + warpM + mt * 16 + gr;
        float* r0 = sp + (size_t)m * CCH + tn * 64 + warpN + qp * 2;
        float* r1 = sp + (size_t)(m + 8) * CCH + tn * 64 + warpN + qp * 2;
#pragma unroll
        for (int nt = 0; nt < 4; nt++) {
            *(float2*)(r0 + nt * 8) = make_float2(acc[mt][nt][0], acc[mt][nt][1]);
            *(float2*)(r1 + nt * 8) = make_float2(acc[mt][nt][2], acc[mt][nt][3]);
        }
    }
}

// ---------------- kernel 2: reduce split-K partials (mirror lower) ----------
__global__ void s_reduce_kernel() {
    int gid = blockIdx.x * blockDim.x + threadIdx.x;
    if (gid >= BATCH * CCH * CCH) return;
    int b = gid / (CCH * CCH), mn = gid % (CCH * CCH);
    int m = mn / CCH, n = mn % CCH;
    int off = ((m >> 6) <= (n >> 6)) ? (m * CCH + n) : (n * CCH + m);
    const float* base = g_Spart + (size_t)b * SSPLIT * CCH * CCH;
    float s = 0.f;
#pragma unroll
    for (int ks = 0; ks < SSPLIT; ks++)
        s += base[(size_t)ks * CCH * CCH + off];
    g_S[gid] = s;
}

// ---------------- kernel 3: per-(b,h) attention -> Meff (bf16 hi/lo) --------
__global__ void attn_build_kernel(const float* __restrict__ w_qkv,
                                  const float* __restrict__ temperature) {
    const int h = blockIdx.x, b = blockIdx.y, t = threadIdx.x;

    __shared__ float sWq[HD][196];
    __shared__ float sWk[HD][196];
    __shared__ float sT[2 * HD][196];
    __shared__ float sG[HD][HD];
    __shared__ float sAttn[HD][HD];
    __shared__ float sQn[HD], sKn[HD];

    for (int i = t; i < HD * CCH; i += 192) {
        int c = i / CCH, j = i % CCH;
        sWq[c][j] = w_qkv[(h * HD + c) * CCH + j];
        sWk[c][j] = w_qkv[(CCH + h * HD + c) * CCH + j];
    }
    __syncthreads();

    {
        float tq[HD] = {}, tk[HD] = {};
        const float* Sb = g_S + b * CCH * CCH;
        for (int m = 0; m < CCH; m++) {
            float s = Sb[m * CCH + t];
#pragma unroll
            for (int c = 0; c < HD; c++) { tq[c] += sWq[c][m] * s; tk[c] += sWk[c][m] * s; }
        }
#pragma unroll
        for (int c = 0; c < HD; c++) { sT[c][t] = tq[c]; sT[HD + c][t] = tk[c]; }
    }
    __syncthreads();

    if (t < 144) {
        int c = t / HD, d = t % HD;
        float s = 0.f;
        for (int j = 0; j < CCH; j++) s += sT[c][j] * sWk[d][j];
        sG[c][d] = s;
    } else if (t < 156) {
        int c = t - 144; float s = 0.f;
        for (int j = 0; j < CCH; j++) s += sT[c][j] * sWq[c][j];
        sQn[c] = s;
    } else if (t < 168) {
        int c = t - 156; float s = 0.f;
        for (int j = 0; j < CCH; j++) s += sT[HD + c][j] * sWk[c][j];
        sKn[c] = s;
    }
    __syncthreads();

    if (t < HD) {
        float temp = temperature[h];
        float qn = fmaxf(sqrtf(fmaxf(sQn[t], 0.f)), 1e-12f);
        float lg[HD];
        float mx = -1e30f;
#pragma unroll
        for (int d = 0; d < HD; d++) {
            float kn = fmaxf(sqrtf(fmaxf(sKn[d], 0.f)), 1e-12f);
            lg[d] = sG[t][d] * temp / (qn * kn);
            mx = fmaxf(mx, lg[d]);
        }
        float sum = 0.f;
#pragma unroll
        for (int d = 0; d < HD; d++) { lg[d] = expf(lg[d] - mx); sum += lg[d]; }
        float inv = 1.f / sum;
#pragma unroll
        for (int d = 0; d < HD; d++) sAttn[t][d] = lg[d] * inv;
    }
    float (*sWv)[196] = sT;
    for (int i = t; i < HD * CCH; i += 192) {
        int c = i / CCH, j = i % CCH;
        sWv[c][j] = w_qkv[(2 * CCH + h * HD + c) * CCH + j];
    }
    __syncthreads();

#pragma unroll
    for (int c = 0; c < HD; c++) {
        float s = 0.f;
#pragma unroll
        for (int d = 0; d < HD; d++) s += sAttn[c][d] * sWv[d][t];
        size_t idx = (size_t)(b * CCH + h * HD + c) * CCH + t;
        unsigned short hh, ll;
        split_bf16(s, hh, ll);
        g_MHi[idx] = hh; g_MLo[idx] = ll;
    }
}

// ---------------- kernel 3b: Wproj -> bf16 hi/lo ----------------------------
__global__ void wconv_kernel(const float* __restrict__ w_proj) {
    int gid = blockIdx.x * blockDim.x + threadIdx.x;
    if (gid >= CCH * CCH) return;
    unsigned short hh, ll;
    split_bf16(w_proj[gid], hh, ll);
    g_WHi[gid] = hh; g_WLo[gid] = ll;
}

// ---------------- kernel 3c: X -> XT hi/lo [b][p][k]  AND X hi/lo [b][k][p] --
__global__ void xt_kernel(const float* __restrict__ x) {
    const int b = blockIdx.z;
    const int k0 = blockIdx.y * 32, p0 = blockIdx.x * 32;
    __shared__ float sm[32][33];
    const int tx = threadIdx.x & 31, ty = threadIdx.x >> 5;

#pragma unroll
    for (int i = 0; i < 4; i++) {
        int k = k0 + ty + i * 8;
        float v = x[((size_t)b * CCH + k) * HW + p0 + tx];
        sm[ty + i * 8][tx] = v;
        unsigned short hh, ll;
        split_bf16(v, hh, ll);
        size_t o = ((size_t)b * CCH + k) * HW + p0 + tx;
        g_Xhi[o] = hh;
        g_Xlo[o] = ll;
    }
    __syncthreads();
#pragma unroll
    for (int i = 0; i < 4; i++) {
        int p = p0 + ty + i * 8;
        int k = k0 + tx;
        float v = sm[tx][ty + i * 8];
        unsigned short hh, ll;
        split_bf16(v, hh, ll);
        size_t o = ((size_t)b * HW + p) * CCH + k;
        g_XThi[o] = hh;
        g_XTlo[o] = ll;
    }
}

// ---------------- kernel 4: mma.sync GEMM  C[b] = A[b] @ B[b]^T ---------------
#define SA32 20                 // smem row stride in u32 (40 bf16)
#define BUF_U32 12800           // per-buffer u32 size
#define OFF_ALO 3840
#define OFF_BHI 7680
#define OFF_BLO 10240
#define GEMM_SMEM (2 * BUF_U32 * 4)   // 102400 bytes

__global__ void __launch_bounds__(256, 1)
gemm_mma_kernel(const unsigned short* __restrict__ Ahi,
                const unsigned short* __restrict__ Alo,
                size_t aStride,
                const unsigned short* __restrict__ BThi,
                const unsigned short* __restrict__ BTlo,
                float* __restrict__ C) {
    extern __shared__ uint32_t sm32[];
    const int t = threadIdx.x;
    const int b = blockIdx.z;
    const int n0 = blockIdx.x * 128;
    const int warp = t >> 5, lane = t & 31;
    const int wm = warp & 3, wn = warp >> 2;
    const int warpM = wm * 48, warpN = wn * 64;
    const int gr = lane >> 2, qp = lane & 3;

    const unsigned short* Ah = Ahi + (size_t)b * aStride;
    const unsigned short* Al = Alo + (size_t)b * aStride;
    const unsigned short* Bh = BThi + ((size_t)b * HW + n0) * CCH;
    const unsigned short* Bl = BTlo + ((size_t)b * HW + n0) * CCH;

    const uint32_t smbase = smem_to_u32(sm32);

    float acc[3][8][4] = {};

    auto issue_chunk = [&](int buf, int kc) {
        const uint32_t sb = smbase + buf * (BUF_U32 * 4);
        const int kb = kc * 32;
#pragma unroll
        for (int i = t; i < 768; i += 256) {
            int row = i >> 2, q = i & 3;
            uint32_t dst = sb + (row * SA32 + q * 4) * 4;
            cp_async16(dst,                Ah + (size_t)row * CCH + kb + q * 8);
            cp_async16(dst + OFF_ALO * 4,  Al + (size_t)row * CCH + kb + q * 8);
        }
#pragma unroll
        for (int i = t; i < 512; i += 256) {
            int row = i >> 2, q = i & 3;
            uint32_t dst = sb + (OFF_BHI + row * SA32 + q * 4) * 4;
            cp_async16(dst,                       Bh + (size_t)row * CCH + kb + q * 8);
            cp_async16(dst + (OFF_BLO - OFF_BHI) * 4, Bl + (size_t)row * CCH + kb + q * 8);
        }
        CP_COMMIT();
    };

    issue_chunk(0, 0);

    int buf = 0;
    for (int kc = 0; kc < 6; kc++) {
        if (kc < 5) {
            issue_chunk(buf ^ 1, kc + 1);
            CP_WAIT(1);
        } else {
            CP_WAIT(0);
        }
        __syncthreads();

        const uint32_t* S = sm32 + buf * BUF_U32;
#pragma unroll
        for (int ks = 0; ks < 2; ks++) {
            const int k8 = ks * 8;
            uint32_t ah[3][4], al[3][4], bh[8][2], bl[8][2];
#pragma unroll
            for (int mt = 0; mt < 3; mt++) {
                int base = (warpM + mt * 16 + gr) * SA32 + k8 + qp;
                ah[mt][0] = S[base];           ah[mt][1] = S[base + 8 * SA32];
                ah[mt][2] = S[base + 4];       ah[mt][3] = S[base + 8 * SA32 + 4];
                al[mt][0] = S[OFF_ALO + base];           al[mt][1] = S[OFF_ALO + base + 8 * SA32];
                al[mt][2] = S[OFF_ALO + base + 4];       al[mt][3] = S[OFF_ALO + base + 8 * SA32 + 4];
            }
#pragma unroll
            for (int nt = 0; nt < 8; nt++) {
                int base = (warpN + nt * 8 + gr) * SA32 + k8 + qp;
                bh[nt][0] = S[OFF_BHI + base]; bh[nt][1] = S[OFF_BHI + base + 4];
                bl[nt][0] = S[OFF_BLO + base]; bl[nt][1] = S[OFF_BLO + base + 4];
            }
#pragma unroll
            for (int mt = 0; mt < 3; mt++)
#pragma unroll
                for (int nt = 0; nt < 8; nt++) {
                    mma_bf16(acc[mt][nt], ah[mt], bh[nt]);
                    mma_bf16(acc[mt][nt], ah[mt], bl[nt]);
                    mma_bf16(acc[mt][nt], al[mt], bh[nt]);
                }
        }
        __syncthreads();
        buf ^= 1;
    }

#pragma unroll
    for (int mt = 0; mt < 3; mt++) {
        int m = warpM + mt * 16 + gr;
        float* c0 = C + ((size_t)b * CCH + m) * HW + n0 + warpN + qp * 2;
        float* c1 = C + ((size_t)b * CCH + m + 8) * HW + n0 + warpN + qp * 2;
#pragma unroll
        for (int nt = 0; nt < 8; nt++) {
            *(float2*)(c0 + nt * 8) = make_float2(acc[mt][nt][0], acc[mt][nt][1]);
            *(float2*)(c1 + nt * 8) = make_float2(acc[mt][nt][2], acc[mt][nt][3]);
        }
    }
}

// ---------------- kernel 6: depthwise 3x3 -> Z^T bf16 hi/lo [b][p][c] --------
__global__ void dwconv_t_kernel(const float* __restrict__ wdw) {
    const int b = blockIdx.z;
    const int c0 = blockIdx.y * 32;
    const int p0 = blockIdx.x * 32;
    const int y  = p0 >> 7;
    const int x0 = p0 & 127;

    __shared__ float sw[32][9];
    __shared__ float st[32][33];   // [px][chLocal]

    const int t = threadIdx.x;
    for (int idx = t; idx < 288; idx += 256)
        sw[idx / 9][idx % 9] = wdw[(c0 + idx / 9) * 9 + idx % 9];
    __syncthreads();

    const int tx = t & 31;      // px
    const int tg = t >> 5;      // 0..7
    const int xx = x0 + tx;

#pragma unroll
    for (int i = 0; i < 4; i++) {
        int chL = tg + i * 8;
        const float* Yc = g_Y + ((size_t)b * CCH + c0 + chL) * HW;
        float acc = 0.f;
#pragma unroll
        for (int ky = 0; ky < 3; ky++) {
            int sy = y + ky - 1;
            if (sy < 0 || sy >= 128) continue;
#pragma unroll
            for (int kx = 0; kx < 3; kx++) {
                int sx = xx + kx - 1;
                if (sx < 0 || sx >= 128) continue;
                acc += sw[chL][ky * 3 + kx] * __ldg(Yc + sy * 128 + sx);
            }
        }
        st[tx][chL] = acc;
    }
    __syncthreads();

    const int row = t >> 3;
    const int ch4 = (t & 7) * 4;
    float v0 = st[row][ch4 + 0], v1 = st[row][ch4 + 1];
    float v2 = st[row][ch4 + 2], v3 = st[row][ch4 + 3];
    unsigned short h0, l0, h1, l1, h2, l2, h3, l3;
    split_bf16(v0, h0, l0); split_bf16(v1, h1, l1);
    split_bf16(v2, h2, l2); split_bf16(v3, h3, l3);
    size_t o = ((size_t)b * HW + p0 + row) * CCH + c0 + ch4;
    *(uint32_t*)(g_ZThi + o)     = (uint32_t)h0 | ((uint32_t)h1 << 16);
    *(uint32_t*)(g_ZThi + o + 2) = (uint32_t)h2 | ((uint32_t)h3 << 16);
    *(uint32_t*)(g_ZTlo + o)     = (uint32_t)l0 | ((uint32_t)l1 << 16);
    *(uint32_t*)(g_ZTlo + o + 2) = (uint32_t)l2 | ((uint32_t)l3 << 16);
}

// ---------------- launch ----------------
extern "C" void kernel_launch(void* const* d_in, const int* in_sizes, int n_in,
                              void* d_out, int out_size) {
    const float* x           = (const float*)d_in[0];
    const float* w_qkv       = (const float*)d_in[1];
    const float* w_dw        = (const float*)d_in[2];
    const float* w_proj      = (const float*)d_in[3];
    const float* temperature = (const float*)d_in[4];
    float* out = (float*)d_out;

    cudaFuncSetAttribute(gemm_mma_kernel,
                         cudaFuncAttributeMaxDynamicSharedMemorySize, GEMM_SMEM);

    float* pY;
    unsigned short *pMHi, *pMLo, *pWHi, *pWLo, *pXThi, *pXTlo, *pZThi, *pZTlo;
    cudaGetSymbolAddress((void**)&pY, g_Y);
    cudaGetSymbolAddress((void**)&pMHi, g_MHi);
    cudaGetSymbolAddress((void**)&pMLo, g_MLo);
    cudaGetSymbolAddress((void**)&pWHi, g_WHi);
    cudaGetSymbolAddress((void**)&pWLo, g_WLo);
    cudaGetSymbolAddress((void**)&pXThi, g_XThi);
    cudaGetSymbolAddress((void**)&pXTlo, g_XTlo);
    cudaGetSymbolAddress((void**)&pZThi, g_ZThi);
    cudaGetSymbolAddress((void**)&pZTlo, g_ZTlo);

    // 0) X -> bf16 hi/lo in both layouts
    xt_kernel<<<dim3(HW / 32, CCH / 32, BATCH), 256>>>(x);
    wconv_kernel<<<(CCH * CCH + 255) / 256, 256>>>(w_proj);

    // 1) S = X X^T (tensor-core split-K partials + deterministic mirror-reduce)
    s_mma_kernel<<<dim3(6, SSPLIT, BATCH), 128>>>();
    s_reduce_kernel<<<(BATCH * CCH * CCH + 255) / 256, 256>>>();

    // 2) attention -> Meff (bf16 hi/lo)
    attn_build_kernel<<<dim3(HEADS, BATCH), 192>>>(w_qkv, temperature);

    // 3) Y = Meff @ X   (mma.sync split-bf16)
    gemm_mma_kernel<<<dim3(HW / 128, 1, BATCH), 256, GEMM_SMEM>>>(
        pMHi, pMLo, (size_t)CCH * CCH, pXThi, pXTlo, pY);

    // 4) depthwise 3x3 -> Z^T bf16 hi/lo
    dwconv_t_kernel<<<dim3(HW / 32, CCH / 32, BATCH), 256>>>(w_dw);

    // 5) out = Wproj @ Z   (mma.sync split-bf16)
    gemm_mma_kernel<<<dim3(HW / 128, 1, BATCH), 256, GEMM_SMEM>>>(
        pWHi, pWLo, (size_t)0, pZThi, pZTlo, out);
}

// round 11
// speedup vs baseline: 1.0013x; 1.0012x over previous
#include <cuda_runtime.h>
#include <cuda_bf16.h>
#include <math.h>
#include <stdint.h>

#define BATCH 8
#define CCH 192
#define HEADS 16
#define HD 12
#define HW 16384
#define SSPLIT 16
#define SKCH 1024   // HW / SSPLIT

// ---------------- scratch (device globals; no allocation) ----------------
__device__ float g_Spart[BATCH * SSPLIT * CCH * CCH];
__device__ float g_S[BATCH * CCH * CCH];
__device__ float g_Y[(size_t)BATCH * CCH * HW];                 // attention output fp32
__device__ unsigned short g_MHi[BATCH * CCH * CCH];             // Meff bf16 hi
__device__ unsigned short g_MLo[BATCH * CCH * CCH];             // Meff bf16 lo
__device__ unsigned short g_WHi[CCH * CCH];                     // Wproj bf16 hi
__device__ unsigned short g_WLo[CCH * CCH];
__device__ unsigned short g_Xhi[(size_t)BATCH * CCH * HW];      // X bf16 hi [b][c][p]
__device__ unsigned short g_Xlo[(size_t)BATCH * CCH * HW];
__device__ unsigned short g_XThi[(size_t)BATCH * HW * CCH];     // X^T bf16 hi [b][p][k]
__device__ unsigned short g_XTlo[(size_t)BATCH * HW * CCH];
__device__ unsigned short g_ZThi[(size_t)BATCH * HW * CCH];     // dw(Y)^T bf16 hi [b][p][c]
__device__ unsigned short g_ZTlo[(size_t)BATCH * HW * CCH];

__constant__ int c_tm[6] = {0, 0, 0, 1, 1, 2};
__constant__ int c_tn[6] = {0, 1, 2, 1, 2, 2};

__device__ __forceinline__ void split_bf16(float v, unsigned short& h, unsigned short& l) {
    __nv_bfloat16 bh = __float2bfloat16(v);
    float hf = __bfloat162float(bh);
    __nv_bfloat16 bl = __float2bfloat16(v - hf);
    h = __bfloat16_as_ushort(bh);
    l = __bfloat16_as_ushort(bl);
}

__device__ __forceinline__ uint32_t smem_to_u32(const void* smem_ptr) {
    uint32_t addr;
    asm("{ .reg .u64 tmp; cvta.to.shared.u64 tmp, %1; cvt.u32.u64 %0, tmp; }"
        : "=r"(addr) : "l"(smem_ptr));
    return addr;
}
__device__ __forceinline__ void cp_async16(uint32_t dst, const void* src) {
    asm volatile("cp.async.cg.shared.global [%0], [%1], 16;" :: "r"(dst), "l"(src) : "memory");
}
#define CP_COMMIT() asm volatile("cp.async.commit_group;" ::: "memory")
#define CP_WAIT(n)  asm volatile("cp.async.wait_group %0;" :: "n"(n) : "memory")

__device__ __forceinline__ void mma_bf16(float* c, const uint32_t* a, const uint32_t* b) {
    asm volatile(
        "mma.sync.aligned.m16n8k16.row.col.f32.bf16.bf16.f32 "
        "{%0,%1,%2,%3}, {%4,%5,%6,%7}, {%8,%9}, {%0,%1,%2,%3};"
        : "+f"(c[0]), "+f"(c[1]), "+f"(c[2]), "+f"(c[3])
        : "r"(a[0]), "r"(a[1]), "r"(a[2]), "r"(a[3]), "r"(b[0]), "r"(b[1]));
}

// ---------------- kernel 1: S partials = X X^T via mma (split-bf16) ----------
// grid (6 upper tile-pairs, SSPLIT, BATCH), 128 threads.
// 64x64 tile, warp grid 2x2 (warp tile 32x32), K-chunk 1024, cp.async x2 buf.
#define S_SA 20      // smem row stride in u32 (32 k = 16 u32 + 4 pad)
#define S_AHI 0
#define S_ALO 1280
#define S_BHI 2560
#define S_BLO 3840
#define S_BUF 5120

__global__ void __launch_bounds__(128, 2) s_mma_kernel() {
    __shared__ uint32_t sm32[2 * S_BUF];

    const int tm = c_tm[blockIdx.x], tn = c_tn[blockIdx.x];
    const int ks = blockIdx.y, b = blockIdx.z;
    const int t = threadIdx.x;
    const int warp = t >> 5, lane = t & 31;
    const int wm = warp & 1, wn = warp >> 1;
    const int warpM = wm * 32, warpN = wn * 32;
    const int gr = lane >> 2, qp = lane & 3;

    const size_t k0 = (size_t)ks * SKCH;
    const unsigned short* Ah = g_Xhi + ((size_t)b * CCH + tm * 64) * HW + k0;
    const unsigned short* Al = g_Xlo + ((size_t)b * CCH + tm * 64) * HW + k0;
    const unsigned short* Bh = g_Xhi + ((size_t)b * CCH + tn * 64) * HW + k0;
    const unsigned short* Bl = g_Xlo + ((size_t)b * CCH + tn * 64) * HW + k0;

    const uint32_t smbase = smem_to_u32(sm32);

    float acc[2][4][4] = {};

    auto issue_chunk = [&](int buf, int kc) {
        const uint32_t sb = smbase + buf * (S_BUF * 4);
        const int kb = kc * 32;
        // 64 rows x 4 quads per stream; 256 items, 2 per thread, 4 streams
#pragma unroll
        for (int i = t; i < 256; i += 128) {
            int row = i >> 2, q = i & 3;
            uint32_t dst = sb + (row * S_SA + q * 4) * 4;
            const size_t off = (size_t)row * HW + kb + q * 8;
            cp_async16(dst + S_AHI * 4, Ah + off);
            cp_async16(dst + S_ALO * 4, Al + off);
            cp_async16(dst + S_BHI * 4, Bh + off);
            cp_async16(dst + S_BLO * 4, Bl + off);
        }
        CP_COMMIT();
    };

    issue_chunk(0, 0);

    int buf = 0;
    const int NIT = SKCH / 32;   // 32
    for (int kc = 0; kc < NIT; kc++) {
        if (kc < NIT - 1) {
            issue_chunk(buf ^ 1, kc + 1);
            CP_WAIT(1);
        } else {
            CP_WAIT(0);
        }
        __syncthreads();

        const uint32_t* S = sm32 + buf * S_BUF;
#pragma unroll
        for (int kk = 0; kk < 2; kk++) {
            const int k8 = kk * 8;
            uint32_t ah[2][4], al[2][4], bh[4][2], bl[4][2];
#pragma unroll
            for (int mt = 0; mt < 2; mt++) {
                int base = (warpM + mt * 16 + gr) * S_SA + k8 + qp;
                ah[mt][0] = S[S_AHI + base];     ah[mt][1] = S[S_AHI + base + 8 * S_SA];
                ah[mt][2] = S[S_AHI + base + 4]; ah[mt][3] = S[S_AHI + base + 8 * S_SA + 4];
                al[mt][0] = S[S_ALO + base];     al[mt][1] = S[S_ALO + base + 8 * S_SA];
                al[mt][2] = S[S_ALO + base + 4]; al[mt][3] = S[S_ALO + base + 8 * S_SA + 4];
            }
#pragma unroll
            for (int nt = 0; nt < 4; nt++) {
                int base = (warpN + nt * 8 + gr) * S_SA + k8 + qp;
                bh[nt][0] = S[S_BHI + base]; bh[nt][1] = S[S_BHI + base + 4];
                bl[nt][0] = S[S_BLO + base]; bl[nt][1] = S[S_BLO + base + 4];
            }
#pragma unroll
            for (int mt = 0; mt < 2; mt++)
#pragma unroll
                for (int nt = 0; nt < 4; nt++) {
                    mma_bf16(acc[mt][nt], ah[mt], bh[nt]);
                    mma_bf16(acc[mt][nt], ah[mt], bl[nt]);
                    mma_bf16(acc[mt][nt], al[mt], bh[nt]);
                }
        }
        __syncthreads();
        buf ^= 1;
    }

    float* sp = g_Spart + (size_t)(b * SSPLIT + ks) * CCH * CCH;
#pragma unroll
    for (int mt = 0; mt < 2; mt++) {
        int m = tm * 64 + warpM + mt * 16 + gr;
        float* r0 = sp + (size_t)m * CCH + tn * 64 + warpN + qp * 2;
        float* r1 = sp + (size_t)(m + 8) * CCH + tn * 64 + warpN + qp * 2;
#pragma unroll
        for (int nt = 0; nt < 4; nt++) {
            *(float2*)(r0 + nt * 8) = make_float2(acc[mt][nt][0], acc[mt][nt][1]);
            *(float2*)(r1 + nt * 8) = make_float2(acc[mt][nt][2], acc[mt][nt][3]);
        }
    }
}

// ---------------- kernel 2: reduce split-K partials (mirror lower) ----------
__global__ void s_reduce_kernel() {
    int gid = blockIdx.x * blockDim.x + threadIdx.x;
    if (gid >= BATCH * CCH * CCH) return;
    int b = gid / (CCH * CCH), mn = gid % (CCH * CCH);
    int m = mn / CCH, n = mn % CCH;
    int off = ((m >> 6) <= (n >> 6)) ? (m * CCH + n) : (n * CCH + m);
    const float* base = g_Spart + (size_t)b * SSPLIT * CCH * CCH;
    float s = 0.f;
#pragma unroll
    for (int ks = 0; ks < SSPLIT; ks++)
        s += base[(size_t)ks * CCH * CCH + off];
    g_S[gid] = s;
}

// ---------------- kernel 3: per-(b,h) attention -> Meff (bf16 hi/lo) --------
__global__ void attn_build_kernel(const float* __restrict__ w_qkv,
                                  const float* __restrict__ temperature) {
    const int h = blockIdx.x, b = blockIdx.y, t = threadIdx.x;

    __shared__ float sWq[HD][196];
    __shared__ float sWk[HD][196];
    __shared__ float sT[2 * HD][196];
    __shared__ float sG[HD][HD];
    __shared__ float sAttn[HD][HD];
    __shared__ float sQn[HD], sKn[HD];

    for (int i = t; i < HD * CCH; i += 192) {
        int c = i / CCH, j = i % CCH;
        sWq[c][j] = w_qkv[(h * HD + c) * CCH + j];
        sWk[c][j] = w_qkv[(CCH + h * HD + c) * CCH + j];
    }
    __syncthreads();

    {
        float tq[HD] = {}, tk[HD] = {};
        const float* Sb = g_S + b * CCH * CCH;
        for (int m = 0; m < CCH; m++) {
            float s = Sb[m * CCH + t];
#pragma unroll
            for (int c = 0; c < HD; c++) { tq[c] += sWq[c][m] * s; tk[c] += sWk[c][m] * s; }
        }
#pragma unroll
        for (int c = 0; c < HD; c++) { sT[c][t] = tq[c]; sT[HD + c][t] = tk[c]; }
    }
    __syncthreads();

    if (t < 144) {
        int c = t / HD, d = t % HD;
        float s = 0.f;
        for (int j = 0; j < CCH; j++) s += sT[c][j] * sWk[d][j];
        sG[c][d] = s;
    } else if (t < 156) {
        int c = t - 144; float s = 0.f;
        for (int j = 0; j < CCH; j++) s += sT[c][j] * sWq[c][j];
        sQn[c] = s;
    } else if (t < 168) {
        int c = t - 156; float s = 0.f;
        for (int j = 0; j < CCH; j++) s += sT[HD + c][j] * sWk[c][j];
        sKn[c] = s;
    }
    __syncthreads();

    if (t < HD) {
        float temp = temperature[h];
        float qn = fmaxf(sqrtf(fmaxf(sQn[t], 0.f)), 1e-12f);
        float lg[HD];
        float mx = -1e30f;
#pragma unroll
        for (int d = 0; d < HD; d++) {
            float kn = fmaxf(sqrtf(fmaxf(sKn[d], 0.f)), 1e-12f);
            lg[d] = sG[t][d] * temp / (qn * kn);
            mx = fmaxf(mx, lg[d]);
        }
        float sum = 0.f;
#pragma unroll
        for (int d = 0; d < HD; d++) { lg[d] = expf(lg[d] - mx); sum += lg[d]; }
        float inv = 1.f / sum;
#pragma unroll
        for (int d = 0; d < HD; d++) sAttn[t][d] = lg[d] * inv;
    }
    float (*sWv)[196] = sT;
    for (int i = t; i < HD * CCH; i += 192) {
        int c = i / CCH, j = i % CCH;
        sWv[c][j] = w_qkv[(2 * CCH + h * HD + c) * CCH + j];
    }
    __syncthreads();

#pragma unroll
    for (int c = 0; c < HD; c++) {
        float s = 0.f;
#pragma unroll
        for (int d = 0; d < HD; d++) s += sAttn[c][d] * sWv[d][t];
        size_t idx = (size_t)(b * CCH + h * HD + c) * CCH + t;
        unsigned short hh, ll;
        split_bf16(s, hh, ll);
        g_MHi[idx] = hh; g_MLo[idx] = ll;
    }
}

// ---------------- kernel 3b: Wproj -> bf16 hi/lo ----------------------------
__global__ void wconv_kernel(const float* __restrict__ w_proj) {
    int gid = blockIdx.x * blockDim.x + threadIdx.x;
    if (gid >= CCH * CCH) return;
    unsigned short hh, ll;
    split_bf16(w_proj[gid], hh, ll);
    g_WHi[gid] = hh; g_WLo[gid] = ll;
}

// ---------------- kernel 3c: X -> XT hi/lo [b][p][k]  AND X hi/lo [b][k][p] --
__global__ void xt_kernel(const float* __restrict__ x) {
    const int b = blockIdx.z;
    const int k0 = blockIdx.y * 32, p0 = blockIdx.x * 32;
    __shared__ float sm[32][33];
    const int tx = threadIdx.x & 31, ty = threadIdx.x >> 5;

#pragma unroll
    for (int i = 0; i < 4; i++) {
        int k = k0 + ty + i * 8;
        float v = x[((size_t)b * CCH + k) * HW + p0 + tx];
        sm[ty + i * 8][tx] = v;
        unsigned short hh, ll;
        split_bf16(v, hh, ll);
        size_t o = ((size_t)b * CCH + k) * HW + p0 + tx;
        g_Xhi[o] = hh;
        g_Xlo[o] = ll;
    }
    __syncthreads();
#pragma unroll
    for (int i = 0; i < 4; i++) {
        int p = p0 + ty + i * 8;
        int k = k0 + tx;
        float v = sm[tx][ty + i * 8];
        unsigned short hh, ll;
        split_bf16(v, hh, ll);
        size_t o = ((size_t)b * HW + p) * CCH + k;
        g_XThi[o] = hh;
        g_XTlo[o] = ll;
    }
}

// ---------------- kernel 4: mma.sync GEMM  C[b] = A[b] @ B[b]^T ---------------
#define SA32 20                 // smem row stride in u32 (40 bf16)
#define BUF_U32 12800           // per-buffer u32 size
#define OFF_ALO 3840
#define OFF_BHI 7680
#define OFF_BLO 10240
#define GEMM_SMEM (2 * BUF_U32 * 4)   // 102400 bytes

__global__ void __launch_bounds__(256, 1)
gemm_mma_kernel(const unsigned short* __restrict__ Ahi,
                const unsigned short* __restrict__ Alo,
                size_t aStride,
                const unsigned short* __restrict__ BThi,
                const unsigned short* __restrict__ BTlo,
                float* __restrict__ C) {
    extern __shared__ uint32_t sm32[];
    const int t = threadIdx.x;
    const int b = blockIdx.z;
    const int n0 = blockIdx.x * 128;
    const int warp = t >> 5, lane = t & 31;
    const int wm = warp & 3, wn = warp >> 2;
    const int warpM = wm * 48, warpN = wn * 64;
    const int gr = lane >> 2, qp = lane & 3;

    const unsigned short* Ah = Ahi + (size_t)b * aStride;
    const unsigned short* Al = Alo + (size_t)b * aStride;
    const unsigned short* Bh = BThi + ((size_t)b * HW + n0) * CCH;
    const unsigned short* Bl = BTlo + ((size_t)b * HW + n0) * CCH;

    const uint32_t smbase = smem_to_u32(sm32);

    float acc[3][8][4] = {};

    auto issue_chunk = [&](int buf, int kc) {
        const uint32_t sb = smbase + buf * (BUF_U32 * 4);
        const int kb = kc * 32;
#pragma unroll
        for (int i = t; i < 768; i += 256) {
            int row = i >> 2, q = i & 3;
            uint32_t dst = sb + (row * SA32 + q * 4) * 4;
            cp_async16(dst,                Ah + (size_t)row * CCH + kb + q * 8);
            cp_async16(dst + OFF_ALO * 4,  Al + (size_t)row * CCH + kb + q * 8);
        }
#pragma unroll
        for (int i = t; i < 512; i += 256) {
            int row = i >> 2, q = i & 3;
            uint32_t dst = sb + (OFF_BHI + row * SA32 + q * 4) * 4;
            cp_async16(dst,                       Bh + (size_t)row * CCH + kb + q * 8);
            cp_async16(dst + (OFF_BLO - OFF_BHI) * 4, Bl + (size_t)row * CCH + kb + q * 8);
        }
        CP_COMMIT();
    };

    issue_chunk(0, 0);

    int buf = 0;
    for (int kc = 0; kc < 6; kc++) {
        if (kc < 5) {
            issue_chunk(buf ^ 1, kc + 1);
            CP_WAIT(1);
        } else {
            CP_WAIT(0);
        }
        __syncthreads();

        const uint32_t* S = sm32 + buf * BUF_U32;
#pragma unroll
        for (int ks = 0; ks < 2; ks++) {
            const int k8 = ks * 8;
            uint32_t ah[3][4], al[3][4], bh[8][2], bl[8][2];
#pragma unroll
            for (int mt = 0; mt < 3; mt++) {
                int base = (warpM + mt * 16 + gr) * SA32 + k8 + qp;
                ah[mt][0] = S[base];           ah[mt][1] = S[base + 8 * SA32];
                ah[mt][2] = S[base + 4];       ah[mt][3] = S[base + 8 * SA32 + 4];
                al[mt][0] = S[OFF_ALO + base];           al[mt][1] = S[OFF_ALO + base + 8 * SA32];
                al[mt][2] = S[OFF_ALO + base + 4];       al[mt][3] = S[OFF_ALO + base + 8 * SA32 + 4];
            }
#pragma unroll
            for (int nt = 0; nt < 8; nt++) {
                int base = (warpN + nt * 8 + gr) * SA32 + k8 + qp;
                bh[nt][0] = S[OFF_BHI + base]; bh[nt][1] = S[OFF_BHI + base + 4];
                bl[nt][0] = S[OFF_BLO + base]; bl[nt][1] = S[OFF_BLO + base + 4];
            }
#pragma unroll
            for (int mt = 0; mt < 3; mt++)
#pragma unroll
                for (int nt = 0; nt < 8; nt++) {
                    mma_bf16(acc[mt][nt], ah[mt], bh[nt]);
                    mma_bf16(acc[mt][nt], ah[mt], bl[nt]);
                    mma_bf16(acc[mt][nt], al[mt], bh[nt]);
                }
        }
        __syncthreads();
        buf ^= 1;
    }

#pragma unroll
    for (int mt = 0; mt < 3; mt++) {
        int m = warpM + mt * 16 + gr;
        float* c0 = C + ((size_t)b * CCH + m) * HW + n0 + warpN + qp * 2;
        float* c1 = C + ((size_t)b * CCH + m + 8) * HW + n0 + warpN + qp * 2;
#pragma unroll
        for (int nt = 0; nt < 8; nt++) {
            *(float2*)(c0 + nt * 8) = make_float2(acc[mt][nt][0], acc[mt][nt][1]);
            *(float2*)(c1 + nt * 8) = make_float2(acc[mt][nt][2], acc[mt][nt][3]);
        }
    }
}

// ---------------- kernel 6: depthwise 3x3 -> Z^T bf16 hi/lo [b][p][c] --------
__global__ void dwconv_t_kernel(const float* __restrict__ wdw) {
    const int b = blockIdx.z;
    const int c0 = blockIdx.y * 32;
    const int p0 = blockIdx.x * 32;
    const int y  = p0 >> 7;
    const int x0 = p0 & 127;

    __shared__ float sw[32][9];
    __shared__ float st[32][33];   // [px][chLocal]

    const int t = threadIdx.x;
    for (int idx = t; idx < 288; idx += 256)
        sw[idx / 9][idx % 9] = wdw[(c0 + idx / 9) * 9 + idx % 9];
    __syncthreads();

    const int tx = t & 31;      // px
    const int tg = t >> 5;      // 0..7
    const int xx = x0 + tx;

#pragma unroll
    for (int i = 0; i < 4; i++) {
        int chL = tg + i * 8;
        const float* Yc = g_Y + ((size_t)b * CCH + c0 + chL) * HW;
        float acc = 0.f;
#pragma unroll
        for (int ky = 0; ky < 3; ky++) {
            int sy = y + ky - 1;
            if (sy < 0 || sy >= 128) continue;
#pragma unroll
            for (int kx = 0; kx < 3; kx++) {
                int sx = xx + kx - 1;
                if (sx < 0 || sx >= 128) continue;
                acc += sw[chL][ky * 3 + kx] * __ldg(Yc + sy * 128 + sx);
            }
        }
        st[tx][chL] = acc;
    }
    __syncthreads();

    const int row = t >> 3;
    const int ch4 = (t & 7) * 4;
    float v0 = st[row][ch4 + 0], v1 = st[row][ch4 + 1];
    float v2 = st[row][ch4 + 2], v3 = st[row][ch4 + 3];
    unsigned short h0, l0, h1, l1, h2, l2, h3, l3;
    split_bf16(v0, h0, l0); split_bf16(v1, h1, l1);
    split_bf16(v2, h2, l2); split_bf16(v3, h3, l3);
    size_t o = ((size_t)b * HW + p0 + row) * CCH + c0 + ch4;
    *(uint32_t*)(g_ZThi + o)     = (uint32_t)h0 | ((uint32_t)h1 << 16);
    *(uint32_t*)(g_ZThi + o + 2) = (uint32_t)h2 | ((uint32_t)h3 << 16);
    *(uint32_t*)(g_ZTlo + o)     = (uint32_t)l0 | ((uint32_t)l1 << 16);
    *(uint32_t*)(g_ZTlo + o + 2) = (uint32_t)l2 | ((uint32_t)l3 << 16);
}

// ---------------- launch ----------------
extern "C" void kernel_launch(void* const* d_in, const int* in_sizes, int n_in,
                              void* d_out, int out_size) {
    const float* x           = (const float*)d_in[0];
    const float* w_qkv       = (const float*)d_in[1];
    const float* w_dw        = (const float*)d_in[2];
    const float* w_proj      = (const float*)d_in[3];
    const float* temperature = (const float*)d_in[4];
    float* out = (float*)d_out;

    cudaFuncSetAttribute(gemm_mma_kernel,
                         cudaFuncAttributeMaxDynamicSharedMemorySize, GEMM_SMEM);

    float* pY;
    unsigned short *pMHi, *pMLo, *pWHi, *pWLo, *pXThi, *pXTlo, *pZThi, *pZTlo;
    cudaGetSymbolAddress((void**)&pY, g_Y);
    cudaGetSymbolAddress((void**)&pMHi, g_MHi);
    cudaGetSymbolAddress((void**)&pMLo, g_MLo);
    cudaGetSymbolAddress((void**)&pWHi, g_WHi);
    cudaGetSymbolAddress((void**)&pWLo, g_WLo);
    cudaGetSymbolAddress((void**)&pXThi, g_XThi);
    cudaGetSymbolAddress((void**)&pXTlo, g_XTlo);
    cudaGetSymbolAddress((void**)&pZThi, g_ZThi);
    cudaGetSymbolAddress((void**)&pZTlo, g_ZTlo);

    // 0) X -> bf16 hi/lo in both layouts
    xt_kernel<<<dim3(HW / 32, CCH / 32, BATCH), 256>>>(x);
    wconv_kernel<<<(CCH * CCH + 255) / 256, 256>>>(w_proj);

    // 1) S = X X^T (tensor-core split-K partials + deterministic mirror-reduce)
    s_mma_kernel<<<dim3(6, SSPLIT, BATCH), 128>>>();
    s_reduce_kernel<<<(BATCH * CCH * CCH + 255) / 256, 256>>>();

    // 2) attention -> Meff (bf16 hi/lo)
    attn_build_kernel<<<dim3(HEADS, BATCH), 192>>>(w_qkv, temperature);

    // 3) Y = Meff @ X   (mma.sync split-bf16)
    gemm_mma_kernel<<<dim3(HW / 128, 1, BATCH), 256, GEMM_SMEM>>>(
        pMHi, pMLo, (size_t)CCH * CCH, pXThi, pXTlo, pY);

    // 4) depthwise 3x3 -> Z^T bf16 hi/lo
    dwconv_t_kernel<<<dim3(HW / 32, CCH / 32, BATCH), 256>>>(w_dw);

    // 5) out = Wproj @ Z   (mma.sync split-bf16)
    gemm_mma_kernel<<<dim3(HW / 128, 1, BATCH), 256, GEMM_SMEM>>>(
        pWHi, pWLo, (size_t)0, pZThi, pZTlo, out);
}